// round 8
// baseline (speedup 1.0000x reference)
#include <cuda_runtime.h>
#include <math.h>

namespace {
constexpr int Bn = 4, Cn = 192, Tn = 2048, Hn = 2, Kd = 96;
constexpr int TQ = 128;               // queries per attn block
constexpr int BAND = 256;
constexpr int WIN = 4;
constexpr int SPAN = TQ + 2 * BAND;   // 640
constexpr int NCH = SPAN / 64;        // 10 chunks of 64 keys
constexpr int KVS  = 100;             // mult of 4 (cp.async/LDS.128), rows 16B aligned
constexpr int PSTR = 80;
constexpr int GSTR = 196;             // gemm staging stride: mult of 4 (LDS.128 rows)
constexpr int ATTN_SMEM_FLOATS = TQ * KVS            // qs [128][100]
                               + 2 * 64 * KVS        // Ks, Vs [64][100]
                               + TQ * PSTR           // P [128][80]
                               + TQ * 12             // rq
                               + TQ * 12             // pTap
                               + TQ                  // lr
                               + 260                 // prox
                               + NCH * 256;          // mbs uint[10][256]
constexpr int GEMM_SMEM_BYTES = (128 * GSTR + 64 * GSTR) * 4;   // 150.5KB
}

__device__ __align__(16) float g_q[Bn * Tn * Cn];
__device__ __align__(16) float g_k[Bn * Tn * Cn];
__device__ __align__(16) float g_v[Bn * Tn * Cn];
__device__ __align__(16) float g_att[Bn * Tn * Cn];

typedef unsigned long long u64t;

__device__ __forceinline__ u64t fma2(u64t a, u64t b, u64t c) {
    u64t d;
    asm("fma.rn.f32x2 %0, %1, %2, %3;" : "=l"(d) : "l"(a), "l"(b), "l"(c));
    return d;
}
__device__ __forceinline__ float lohi_sum(u64t v) {
    float2 f = *reinterpret_cast<float2*>(&v);
    return f.x + f.y;
}
__device__ __forceinline__ float2 unpk(u64t v) { return *reinterpret_cast<float2*>(&v); }
__device__ __forceinline__ u64t lds2(const float* p) {
    return *reinterpret_cast<const u64t*>(p);
}
__device__ __forceinline__ u64t dup2(float p) {
    u64t r;
    asm("mov.b64 %0, {%1, %1};" : "=l"(r) : "f"(p));
    return r;
}
__device__ __forceinline__ void cpa16(float* s, const float* g) {
    asm volatile("cp.async.cg.shared.global [%0], [%1], 16;"
                 :: "r"((unsigned)__cvta_generic_to_shared(s)), "l"(g));
}
__device__ __forceinline__ void cpa_commit() { asm volatile("cp.async.commit_group;"); }
__device__ __forceinline__ void cpa_wait0()  { asm volatile("cp.async.wait_group 0;"); }

// ---------------------------------------------------------------------------
// Q/K/V projections: 128x64 tile, 8x4 microtile, single-fill staging.
// grid (16, 3, 12), block (16,16)
// ---------------------------------------------------------------------------
__global__ void __launch_bounds__(256)
proj_kernel(const float* __restrict__ xin, const float* __restrict__ cin,
            const float* __restrict__ Wq, const float* __restrict__ bq,
            const float* __restrict__ Wk, const float* __restrict__ bk,
            const float* __restrict__ Wv, const float* __restrict__ bv) {
    extern __shared__ float smp[];
    float* a_s = smp;                // [128 t][196 kk]
    float* w_s = smp + 128 * GSTR;   // [64 d][196 kk]
    const int which = blockIdx.z % 3;
    const int b = blockIdx.z / 3;
    const float* in   = (which == 0) ? xin : cin;
    const float* W    = (which == 0) ? Wq : (which == 1) ? Wk : Wv;
    const float* bias = (which == 0) ? bq : (which == 1) ? bk : bv;
    float* out        = (which == 0) ? g_q : (which == 1) ? g_k : g_v;
    const int t0 = blockIdx.x * 128, d0 = blockIdx.y * 64;
    const int tx = threadIdx.x, ty = threadIdx.y, tid = ty * 16 + tx;
    const int lane = tid & 31, wrp = tid >> 5;
    const int la = lane & 3, kl = lane >> 2;
    const float* inb = in + b * Cn * Tn;

    // fill A ([kk][t] -> [t][kk]) 128 rows: 24 float4/thread, batched by r
#pragma unroll
    for (int r = 0; r < 3; r++) {
        float4 va[8];
#pragma unroll
        for (int ph = 0; ph < 8; ph++) {
            int kk = kl + 8 * wrp + 64 * r;
            int t4 = 4 * la + 16 * ph;
            va[ph] = *reinterpret_cast<const float4*>(inb + kk * Tn + t0 + t4);
        }
#pragma unroll
        for (int ph = 0; ph < 8; ph++) {
            int kk = kl + 8 * wrp + 64 * r;
            int t4 = 4 * la + 16 * ph;
            a_s[(t4 + 0) * GSTR + kk] = va[ph].x;
            a_s[(t4 + 1) * GSTR + kk] = va[ph].y;
            a_s[(t4 + 2) * GSTR + kk] = va[ph].z;
            a_s[(t4 + 3) * GSTR + kk] = va[ph].w;
        }
    }
    // fill W ([kk][d] -> [d][kk]) 64 rows: 12 float4/thread
#pragma unroll
    for (int r = 0; r < 3; r++) {
        float4 vw[4];
#pragma unroll
        for (int ph = 0; ph < 4; ph++) {
            int kk = kl + 8 * wrp + 64 * r;
            int d4 = 4 * la + 16 * ph;
            vw[ph] = *reinterpret_cast<const float4*>(W + kk * Cn + d0 + d4);
        }
#pragma unroll
        for (int ph = 0; ph < 4; ph++) {
            int kk = kl + 8 * wrp + 64 * r;
            int d4 = 4 * la + 16 * ph;
            w_s[(d4 + 0) * GSTR + kk] = vw[ph].x;
            w_s[(d4 + 1) * GSTR + kk] = vw[ph].y;
            w_s[(d4 + 2) * GSTR + kk] = vw[ph].z;
            w_s[(d4 + 3) * GSTR + kk] = vw[ph].w;
        }
    }
    __syncthreads();

    u64t acc2[8][4] = {};
#pragma unroll 2
    for (int kk = 0; kk < Cn; kk += 4) {
        float4 a4[8];
        u64t w2[4][2];
#pragma unroll
        for (int i = 0; i < 8; i++)
            a4[i] = *reinterpret_cast<const float4*>(&a_s[(ty + 16 * i) * GSTR + kk]);
#pragma unroll
        for (int j = 0; j < 4; j++) {
            w2[j][0] = lds2(&w_s[(tx + 16 * j) * GSTR + kk]);
            w2[j][1] = lds2(&w_s[(tx + 16 * j) * GSTR + kk + 2]);
        }
#pragma unroll
        for (int i = 0; i < 8; i++) {
            const u64t* qa = reinterpret_cast<const u64t*>(&a4[i]);
#pragma unroll
            for (int j = 0; j < 4; j++) {
                acc2[i][j] = fma2(qa[0], w2[j][0], acc2[i][j]);
                acc2[i][j] = fma2(qa[1], w2[j][1], acc2[i][j]);
            }
        }
    }
    float* ob = out + b * Tn * Cn;
#pragma unroll
    for (int i = 0; i < 8; i++) {
        int t = t0 + ty + 16 * i;
#pragma unroll
        for (int j = 0; j < 4; j++) {
            int d = d0 + tx + 16 * j;
            ob[t * Cn + d] = lohi_sum(acc2[i][j]) + bias[d];
        }
    }
}

// ---------------------------------------------------------------------------
// Single-pass banded attention: TQ=128, 8x4 microtile, 1 CTA/SM, one wave.
// grid (16, 8), block (16,16)
// ---------------------------------------------------------------------------
__global__ void __launch_bounds__(256)
attn_kernel(const float* __restrict__ embk, const float* __restrict__ embv,
            const int* __restrict__ mask) {
    extern __shared__ float sm[];
    float* qs   = sm;                     // [128][100]
    float* Ks   = qs + TQ * KVS;          // [64][100]
    float* Vs   = Ks + 64 * KVS;          // [64][100]
    float* P    = Vs + 64 * KVS;          // [128][80]
    float* rq   = P + TQ * PSTR;          // [128][12]
    float* pTap = rq + TQ * 12;           // [128][12]
    float* lr   = pTap + TQ * 12;         // [128]
    float* prox = lr + TQ;                // [260]
    unsigned* mbs = reinterpret_cast<unsigned*>(prox + 260); // [10][256]

    const int tx = threadIdx.x, ty = threadIdx.y;
    const int tid = ty * 16 + tx;
    const int b = blockIdx.y / Hn, h = blockIdx.y % Hn;
    const int t0 = blockIdx.x * TQ;
    const int sbase = t0 - BAND;

    const float* Qb = g_q + (b * Tn) * Cn + h * Kd;
    const float* Kb = g_k + (b * Tn) * Cn + h * Kd;
    const float* Vb = g_v + (b * Tn) * Cn + h * Kd;

    // issue chunk 0 K/V loads
#pragma unroll
    for (int r = 0; r < 6; r++) {
        int idx = tid + 256 * r;
        int row = idx / 24, c4 = (idx % 24) * 4;
        int s = sbase + row;
        int sc = s < 0 ? 0 : (s >= Tn ? Tn - 1 : s);
        cpa16(&Ks[row * KVS + c4], Kb + sc * Cn + c4);
        cpa16(&Vs[row * KVS + c4], Vb + sc * Cn + c4);
    }
    cpa_commit();

    for (int i = tid; i < TQ * 12; i += 256) pTap[i] = 0.f;
    for (int i = tid; i <= BAND; i += 256) prox[i] = log1pf((float)i);

    // load Q (pre-scaled): 128 rows x 96
    const float qsc = 0.10206207261596575f;
#pragma unroll
    for (int r = 0; r < 12; r++) {
        int idx = tid + 256 * r;
        int row = idx / 24, c4 = (idx % 24) * 4;
        float4 v = *reinterpret_cast<const float4*>(Qb + (t0 + row) * Cn + c4);
        float* d = qs + row * KVS + c4;
        d[0] = v.x * qsc; d[1] = v.y * qsc; d[2] = v.z * qsc; d[3] = v.w * qsc;
    }

    // hoist ALL mask loads: 32 bits/chunk/thread
    {
        const int* mb = mask + b * Tn * Tn;
#pragma unroll
        for (int ch = 0; ch < NCH; ch++) {
            unsigned bits = 0;
#pragma unroll
            for (int i = 0; i < 8; i++) {
                int t = t0 + ty + 16 * i;
#pragma unroll
                for (int j = 0; j < 4; j++) {
                    int s = sbase + ch * 64 + tx + 16 * j;
                    int d = s - t;
                    int ad = d < 0 ? -d : d;
                    bool valid = (s >= 0) && (s < Tn) && (ad <= BAND);
                    if (valid) valid = (mb[t * Tn + s] != 0);
                    if (valid) bits |= 1u << (i * 4 + j);
                }
            }
            mbs[ch * 256 + tid] = bits;
        }
    }
    __syncthreads();   // qs visible for rq

    // rel-K per-query logits (128x9)
    for (int idx = tid; idx < TQ * 9; idx += 256) {
        int q = idx / 9, m = idx - q * 9;
        const float* e  = embk + m * Kd;
        const float* qp = qs + q * KVS;
        float s = 0.f;
#pragma unroll 8
        for (int kk = 0; kk < Kd; kk++) s += qp[kk] * e[kk];
        rq[q * 12 + m] = s;
    }

    u64t o2[8][3] = {};    // packed d-pair accumulators, persistent
    float lsum[8] = {};

    for (int ch = 0; ch < NCH; ch++) {
        cpa_wait0();
        __syncthreads();   // Ks/Vs(ch) ready; rq ready (first iter)

        // QK^T: 8 q-rows x 4 keys, q via LDS.128, k via LDS.64 pairs
        u64t acc2[8][4] = {};
#pragma unroll 2
        for (int kk = 0; kk < Kd; kk += 4) {
            float4 q4[8];
            u64t k2[4][2];
#pragma unroll
            for (int i = 0; i < 8; i++)
                q4[i] = *reinterpret_cast<const float4*>(&qs[(ty + 16 * i) * KVS + kk]);
#pragma unroll
            for (int j = 0; j < 4; j++) {
                k2[j][0] = lds2(&Ks[(tx + 16 * j) * KVS + kk]);
                k2[j][1] = lds2(&Ks[(tx + 16 * j) * KVS + kk + 2]);
            }
#pragma unroll
            for (int i = 0; i < 8; i++) {
                const u64t* qa = reinterpret_cast<const u64t*>(&q4[i]);
#pragma unroll
                for (int j = 0; j < 4; j++) {
                    acc2[i][j] = fma2(qa[0], k2[j][0], acc2[i][j]);
                    acc2[i][j] = fma2(qa[1], k2[j][1], acc2[i][j]);
                }
            }
        }

        // epilogue: rel-k tap + proximal bias + mask + exp
        unsigned mbits = mbs[ch * 256 + tid];
#pragma unroll
        for (int i = 0; i < 8; i++) {
            int q = ty + 16 * i, t = t0 + q;
#pragma unroll
            for (int j = 0; j < 4; j++) {
                int sl = tx + 16 * j;
                int s = sbase + ch * 64 + sl;
                int d = s - t;
                int ad = d < 0 ? -d : d;
                float v = lohi_sum(acc2[i][j]);
                if (ad <= WIN) v += rq[q * 12 + d + WIN];
                v -= prox[ad <= BAND ? ad : BAND];
                float e = (mbits >> (i * 4 + j)) & 1u ? __expf(v) : 0.f;
                P[q * PSTR + sl] = e;
                if (ad <= WIN) pTap[q * 12 + d + WIN] = e;
                lsum[i] += e;
            }
        }
        __syncthreads();   // P visible; QK done with Ks

        // O += P @ V: P via LDS.64 sl-pairs, V d-paired, packed accum
#pragma unroll 2
        for (int sl = 0; sl < 64; sl += 2) {
            u64t pp[8], va[3], vb[3];
#pragma unroll
            for (int i = 0; i < 8; i++) pp[i] = lds2(&P[(ty + 16 * i) * PSTR + sl]);
#pragma unroll
            for (int jj = 0; jj < 3; jj++) {
                va[jj] = lds2(&Vs[sl * KVS + 2 * tx + 32 * jj]);
                vb[jj] = lds2(&Vs[(sl + 1) * KVS + 2 * tx + 32 * jj]);
            }
#pragma unroll
            for (int i = 0; i < 8; i++) {
                float2 f = unpk(pp[i]);
                u64t pa = dup2(f.x), pb = dup2(f.y);
#pragma unroll
                for (int jj = 0; jj < 3; jj++) {
                    o2[i][jj] = fma2(pa, va[jj], o2[i][jj]);
                    o2[i][jj] = fma2(pb, vb[jj], o2[i][jj]);
                }
            }
        }
        __syncthreads();   // PV done with Vs/P

        if (ch + 1 < NCH) {
#pragma unroll
            for (int r = 0; r < 6; r++) {
                int idx = tid + 256 * r;
                int row = idx / 24, c4 = (idx % 24) * 4;
                int s = sbase + (ch + 1) * 64 + row;
                int sc = s < 0 ? 0 : (s >= Tn ? Tn - 1 : s);
                cpa16(&Ks[row * KVS + c4], Kb + sc * Cn + c4);
                cpa16(&Vs[row * KVS + c4], Vb + sc * Cn + c4);
            }
            cpa_commit();
        }
    }

    // reduce row sums across the 16 tx lanes
#pragma unroll
    for (int i = 0; i < 8; i++) {
        float l = lsum[i];
        l += __shfl_xor_sync(0xffffffffu, l, 1);
        l += __shfl_xor_sync(0xffffffffu, l, 2);
        l += __shfl_xor_sync(0xffffffffu, l, 4);
        l += __shfl_xor_sync(0xffffffffu, l, 8);
        if (tx == 0) lr[ty + 16 * i] = l;
    }
    __syncthreads();

    // rel-V taps + normalize + store
#pragma unroll
    for (int i = 0; i < 8; i++) {
        int q = ty + 16 * i;
        float inv = 1.0f / lr[q];
#pragma unroll
        for (int m = 0; m < 9; m++) {
            u64t pm = dup2(pTap[q * 12 + m]);
#pragma unroll
            for (int jj = 0; jj < 3; jj++) {
                u64t e2 = *reinterpret_cast<const u64t*>(embv + m * Kd + 2 * tx + 32 * jj);
                o2[i][jj] = fma2(pm, e2, o2[i][jj]);
            }
        }
        float* ob = g_att + (b * Tn + t0 + q) * Cn + h * Kd;
#pragma unroll
        for (int jj = 0; jj < 3; jj++) {
            float2 f = unpk(o2[i][jj]);
            float2 w;
            w.x = f.x * inv;
            w.y = f.y * inv;
            *reinterpret_cast<float2*>(ob + 2 * tx + 32 * jj) = w;
        }
    }
}

// ---------------------------------------------------------------------------
// Output projection + transpose: 128t x 64co tile, microtile 4co x 8t.
// grid (16, 3, 4), block (16,16)
// ---------------------------------------------------------------------------
__global__ void __launch_bounds__(256)
outproj_kernel(const float* __restrict__ Wo, const float* __restrict__ bo,
               float* __restrict__ out) {
    extern __shared__ float smp[];
    float* a_s = smp;                // [128 t][196 dd]
    float* w_s = smp + 128 * GSTR;   // [64 co][196 dd]
    const int b = blockIdx.z;
    const int t0 = blockIdx.x * 128, c0 = blockIdx.y * 64;
    const int tx = threadIdx.x, ty = threadIdx.y, tid = ty * 16 + tx;
    const int lane = tid & 31, wrp = tid >> 5;
    const int la = lane & 3, kl = lane >> 2;
    const float* ab = g_att + b * Tn * Cn;

    // A tile straight copy via cp.async (rows contiguous over dd)
#pragma unroll
    for (int r = 0; r < 24; r++) {
        int idx = tid + 256 * r;
        int t = idx / 48, dq = (idx % 48) * 4;
        cpa16(&a_s[t * GSTR + dq], ab + (t0 + t) * Cn + dq);
    }
    cpa_commit();
    // W transpose [dd][co] -> [co][dd]
#pragma unroll
    for (int r = 0; r < 3; r++) {
        float4 vw[4];
#pragma unroll
        for (int ph = 0; ph < 4; ph++) {
            int kk = kl + 8 * wrp + 64 * r;
            int d4 = 4 * la + 16 * ph;
            vw[ph] = *reinterpret_cast<const float4*>(Wo + kk * Cn + c0 + d4);
        }
#pragma unroll
        for (int ph = 0; ph < 4; ph++) {
            int kk = kl + 8 * wrp + 64 * r;
            int d4 = 4 * la + 16 * ph;
            w_s[(d4 + 0) * GSTR + kk] = vw[ph].x;
            w_s[(d4 + 1) * GSTR + kk] = vw[ph].y;
            w_s[(d4 + 2) * GSTR + kk] = vw[ph].z;
            w_s[(d4 + 3) * GSTR + kk] = vw[ph].w;
        }
    }
    cpa_wait0();
    __syncthreads();

    u64t acc2[4][8] = {};
#pragma unroll 2
    for (int kk = 0; kk < Cn; kk += 4) {
        float4 w4[4];
        u64t a2[8][2];
#pragma unroll
        for (int i = 0; i < 4; i++)
            w4[i] = *reinterpret_cast<const float4*>(&w_s[(ty + 16 * i) * GSTR + kk]);
#pragma unroll
        for (int j = 0; j < 8; j++) {
            a2[j][0] = lds2(&a_s[(tx + 16 * j) * GSTR + kk]);
            a2[j][1] = lds2(&a_s[(tx + 16 * j) * GSTR + kk + 2]);
        }
#pragma unroll
        for (int i = 0; i < 4; i++) {
            const u64t* wa = reinterpret_cast<const u64t*>(&w4[i]);
#pragma unroll
            for (int j = 0; j < 8; j++) {
                acc2[i][j] = fma2(wa[0], a2[j][0], acc2[i][j]);
                acc2[i][j] = fma2(wa[1], a2[j][1], acc2[i][j]);
            }
        }
    }
#pragma unroll
    for (int i = 0; i < 4; i++) {
        int co = c0 + ty + 16 * i;
        float bb = bo[co];
#pragma unroll
        for (int j = 0; j < 8; j++)
            out[(b * Cn + co) * Tn + t0 + tx + 16 * j] = lohi_sum(acc2[i][j]) + bb;
    }
}

// ---------------------------------------------------------------------------
extern "C" void kernel_launch(void* const* d_in, const int* in_sizes, int n_in,
                              void* d_out, int out_size) {
    (void)in_sizes; (void)n_in; (void)out_size;
    const float* x   = (const float*)d_in[0];
    const float* c   = (const float*)d_in[1];
    const float* Wq  = (const float*)d_in[2];
    const float* bq  = (const float*)d_in[3];
    const float* Wk  = (const float*)d_in[4];
    const float* bk  = (const float*)d_in[5];
    const float* Wv  = (const float*)d_in[6];
    const float* bv  = (const float*)d_in[7];
    const float* Wo  = (const float*)d_in[8];
    const float* bo  = (const float*)d_in[9];
    const float* ek  = (const float*)d_in[10];
    const float* ev  = (const float*)d_in[11];
    const int*   msk = (const int*)d_in[12];

    const int attn_smem = ATTN_SMEM_FLOATS * (int)sizeof(float);
    cudaFuncSetAttribute(attn_kernel, cudaFuncAttributeMaxDynamicSharedMemorySize, attn_smem);
    cudaFuncSetAttribute(proj_kernel, cudaFuncAttributeMaxDynamicSharedMemorySize, GEMM_SMEM_BYTES);
    cudaFuncSetAttribute(outproj_kernel, cudaFuncAttributeMaxDynamicSharedMemorySize, GEMM_SMEM_BYTES);

    proj_kernel<<<dim3(Tn / 128, Cn / 64, Bn * 3), dim3(16, 16), GEMM_SMEM_BYTES>>>(
        x, c, Wq, bq, Wk, bk, Wv, bv);
    attn_kernel<<<dim3(Tn / TQ, Bn * Hn), dim3(16, 16), attn_smem>>>(ek, ev, msk);
    outproj_kernel<<<dim3(Tn / 128, Cn / 64, Bn), dim3(16, 16), GEMM_SMEM_BYTES>>>(
        Wo, bo, (float*)d_out);
}

// round 10
// speedup vs baseline: 1.1559x; 1.1559x over previous
#include <cuda_runtime.h>
#include <math.h>

namespace {
constexpr int Bn = 4, Cn = 192, Tn = 2048, Hn = 2, Kd = 96;
constexpr int TQ = 64;
constexpr int BAND = 256;
constexpr int WIN = 4;
constexpr int SPAN = TQ + 2 * BAND;   // 576
constexpr int NCH = SPAN / 64;        // 9
constexpr int KVS  = 100;             // mult of 4 (cp.async 16B rows), even (LDS.64)
constexpr int PSTR = 80;
constexpr int GSTR = 196;             // proj staging stride (R8)
constexpr int ATTN_SMEM_FLOATS = 3 * TQ * KVS   // qs, Ks, Vs
                               + TQ * PSTR      // P
                               + TQ * 12        // rq
                               + TQ * 12        // pTap
                               + TQ             // lr
                               + 260            // prox
                               + 128;           // mrow u64[64]
constexpr int GEMM_SMEM_BYTES = (128 * GSTR + 64 * GSTR) * 4;   // proj (R8)
constexpr int OASTR = 196;
constexpr int OWSTR = 194;
constexpr int OUT_SMEM_BYTES = 64 * (OASTR + OWSTR) * 4;
}

__device__ __align__(16) float g_q[Bn * Tn * Cn];
__device__ __align__(16) float g_k[Bn * Tn * Cn];
__device__ __align__(16) float g_v[Bn * Tn * Cn];
__device__ __align__(16) float g_att[Bn * Tn * Cn];

typedef unsigned long long u64t;

__device__ __forceinline__ u64t fma2(u64t a, u64t b, u64t c) {
    u64t d;
    asm("fma.rn.f32x2 %0, %1, %2, %3;" : "=l"(d) : "l"(a), "l"(b), "l"(c));
    return d;
}
__device__ __forceinline__ float lohi_sum(u64t v) {
    float2 f = *reinterpret_cast<float2*>(&v);
    return f.x + f.y;
}
__device__ __forceinline__ float2 unpk(u64t v) { return *reinterpret_cast<float2*>(&v); }
__device__ __forceinline__ u64t lds2(const float* p) {
    return *reinterpret_cast<const u64t*>(p);
}
__device__ __forceinline__ u64t dup2(float p) {
    u64t r;
    asm("mov.b64 %0, {%1, %1};" : "=l"(r) : "f"(p));
    return r;
}
__device__ __forceinline__ void cpa16(float* s, const float* g) {
    asm volatile("cp.async.cg.shared.global [%0], [%1], 16;"
                 :: "r"((unsigned)__cvta_generic_to_shared(s)), "l"(g));
}
__device__ __forceinline__ void cpa_commit() { asm volatile("cp.async.commit_group;"); }
__device__ __forceinline__ void cpa_wait0()  { asm volatile("cp.async.wait_group 0;"); }

// ---------------------------------------------------------------------------
// Q/K/V projections (R8 version): 128x64 tile, 8x4 microtile, single-fill.
// ---------------------------------------------------------------------------
__global__ void __launch_bounds__(256)
proj_kernel(const float* __restrict__ xin, const float* __restrict__ cin,
            const float* __restrict__ Wq, const float* __restrict__ bq,
            const float* __restrict__ Wk, const float* __restrict__ bk,
            const float* __restrict__ Wv, const float* __restrict__ bv) {
    extern __shared__ float smp[];
    float* a_s = smp;                // [128 t][196 kk]
    float* w_s = smp + 128 * GSTR;   // [64 d][196 kk]
    const int which = blockIdx.z % 3;
    const int b = blockIdx.z / 3;
    const float* in   = (which == 0) ? xin : cin;
    const float* W    = (which == 0) ? Wq : (which == 1) ? Wk : Wv;
    const float* bias = (which == 0) ? bq : (which == 1) ? bk : bv;
    float* out        = (which == 0) ? g_q : (which == 1) ? g_k : g_v;
    const int t0 = blockIdx.x * 128, d0 = blockIdx.y * 64;
    const int tx = threadIdx.x, ty = threadIdx.y, tid = ty * 16 + tx;
    const int lane = tid & 31, wrp = tid >> 5;
    const int la = lane & 3, kl = lane >> 2;
    const float* inb = in + b * Cn * Tn;

#pragma unroll
    for (int r = 0; r < 3; r++) {
        float4 va[8];
#pragma unroll
        for (int ph = 0; ph < 8; ph++) {
            int kk = kl + 8 * wrp + 64 * r;
            int t4 = 4 * la + 16 * ph;
            va[ph] = *reinterpret_cast<const float4*>(inb + kk * Tn + t0 + t4);
        }
#pragma unroll
        for (int ph = 0; ph < 8; ph++) {
            int kk = kl + 8 * wrp + 64 * r;
            int t4 = 4 * la + 16 * ph;
            a_s[(t4 + 0) * GSTR + kk] = va[ph].x;
            a_s[(t4 + 1) * GSTR + kk] = va[ph].y;
            a_s[(t4 + 2) * GSTR + kk] = va[ph].z;
            a_s[(t4 + 3) * GSTR + kk] = va[ph].w;
        }
    }
#pragma unroll
    for (int r = 0; r < 3; r++) {
        float4 vw[4];
#pragma unroll
        for (int ph = 0; ph < 4; ph++) {
            int kk = kl + 8 * wrp + 64 * r;
            int d4 = 4 * la + 16 * ph;
            vw[ph] = *reinterpret_cast<const float4*>(W + kk * Cn + d0 + d4);
        }
#pragma unroll
        for (int ph = 0; ph < 4; ph++) {
            int kk = kl + 8 * wrp + 64 * r;
            int d4 = 4 * la + 16 * ph;
            w_s[(d4 + 0) * GSTR + kk] = vw[ph].x;
            w_s[(d4 + 1) * GSTR + kk] = vw[ph].y;
            w_s[(d4 + 2) * GSTR + kk] = vw[ph].z;
            w_s[(d4 + 3) * GSTR + kk] = vw[ph].w;
        }
    }
    __syncthreads();

    u64t acc2[8][4] = {};
#pragma unroll 2
    for (int kk = 0; kk < Cn; kk += 4) {
        float4 a4[8];
        u64t w2[4][2];
#pragma unroll
        for (int i = 0; i < 8; i++)
            a4[i] = *reinterpret_cast<const float4*>(&a_s[(ty + 16 * i) * GSTR + kk]);
#pragma unroll
        for (int j = 0; j < 4; j++) {
            w2[j][0] = lds2(&w_s[(tx + 16 * j) * GSTR + kk]);
            w2[j][1] = lds2(&w_s[(tx + 16 * j) * GSTR + kk + 2]);
        }
#pragma unroll
        for (int i = 0; i < 8; i++) {
            const u64t* qa = reinterpret_cast<const u64t*>(&a4[i]);
#pragma unroll
            for (int j = 0; j < 4; j++) {
                acc2[i][j] = fma2(qa[0], w2[j][0], acc2[i][j]);
                acc2[i][j] = fma2(qa[1], w2[j][1], acc2[i][j]);
            }
        }
    }
    float* ob = out + b * Tn * Cn;
#pragma unroll
    for (int i = 0; i < 8; i++) {
        int t = t0 + ty + 16 * i;
#pragma unroll
        for (int j = 0; j < 4; j++) {
            int d = d0 + tx + 16 * j;
            ob[t * Cn + d] = lohi_sum(acc2[i][j]) + bias[d];
        }
    }
}

// ---------------------------------------------------------------------------
// Single-pass banded attention (TQ=64, 2 CTAs/SM) with:
//  - warp-ballot mask producer per chunk (coalesced, overlaps cp.async wait)
//  - split K/V prefetch: K overlaps PV, V issued after PV
// ---------------------------------------------------------------------------
__global__ void __launch_bounds__(256, 2)
attn_kernel(const float* __restrict__ embk, const float* __restrict__ embv,
            const int* __restrict__ mask) {
    extern __shared__ float sm[];
    float* qs   = sm;                     // [64][100]
    float* Ks   = qs + TQ * KVS;          // [64][100]
    float* Vs   = Ks + TQ * KVS;          // [64][100]
    float* P    = Vs + TQ * KVS;          // [64][80]
    float* rq   = P + TQ * PSTR;          // [64][12]
    float* pTap = rq + TQ * 12;           // [64][12]
    float* lr   = pTap + TQ * 12;         // [64]
    float* prox = lr + TQ;                // [260]
    u64t*  mrow = reinterpret_cast<u64t*>(prox + 260);  // [64]

    const int tx = threadIdx.x, ty = threadIdx.y;
    const int tid = ty * 16 + tx;
    const int lane = tid & 31, wrp = tid >> 5;
    const int b = blockIdx.y / Hn, h = blockIdx.y % Hn;
    const int t0 = blockIdx.x * TQ;
    const int sbase = t0 - BAND;

    const float* Qb = g_q + (b * Tn) * Cn + h * Kd;
    const float* Kb = g_k + (b * Tn) * Cn + h * Kd;
    const float* Vb = g_v + (b * Tn) * Cn + h * Kd;
    const int* mb = mask + b * Tn * Tn;

    // issue chunk 0 K+V loads
#pragma unroll
    for (int r = 0; r < 6; r++) {
        int idx = tid + 256 * r;
        int row = idx / 24, c4 = (idx % 24) * 4;
        int s = sbase + row;
        int sc = s < 0 ? 0 : (s >= Tn ? Tn - 1 : s);
        cpa16(&Ks[row * KVS + c4], Kb + sc * Cn + c4);
        cpa16(&Vs[row * KVS + c4], Vb + sc * Cn + c4);
    }
    cpa_commit();

    for (int i = tid; i < TQ * 12; i += 256) pTap[i] = 0.f;
    for (int i = tid; i <= BAND; i += 256) prox[i] = log1pf((float)i);

    // load Q (pre-scaled)
    const float qsc = 0.10206207261596575f;
#pragma unroll
    for (int r = 0; r < 6; r++) {
        int idx = tid + 256 * r;
        int row = idx / 24, c4 = (idx % 24) * 4;
        float4 v = *reinterpret_cast<const float4*>(Qb + (t0 + row) * Cn + c4);
        float* d = qs + row * KVS + c4;
        d[0] = v.x * qsc; d[1] = v.y * qsc; d[2] = v.z * qsc; d[3] = v.w * qsc;
    }
    __syncthreads();   // qs visible for rq

    // rel-K per-query logits
    for (int idx = tid; idx < TQ * 9; idx += 256) {
        int q = idx / 9, m = idx - q * 9;
        const float* e  = embk + m * Kd;
        const float* qp = qs + q * KVS;
        float s = 0.f;
#pragma unroll 8
        for (int kk = 0; kk < Kd; kk++) s += qp[kk] * e[kk];
        rq[q * 12 + m] = s;
    }

    float o[4][6] = {};
    float lsum[4] = {};

    for (int ch = 0; ch < NCH; ch++) {
        // mask bits for this chunk: warp w -> rows 8w..8w+7, coalesced LDG +
        // ballot; latency overlaps the cp.async wait below.
        {
            int s0 = sbase + ch * 64;
#pragma unroll
            for (int rr = 0; rr < 8; rr++) {
                int t = t0 + 8 * wrp + rr;
                int s1 = s0 + lane, s2 = s0 + lane + 32;
                int d1 = s1 - t, d2 = s2 - t;
                bool v1 = (s1 >= 0) && (s1 < Tn) && (d1 <= BAND) && (d1 >= -BAND);
                bool v2 = (s2 >= 0) && (s2 < Tn) && (d2 <= BAND) && (d2 >= -BAND);
                if (v1) v1 = (mb[t * Tn + s1] != 0);
                if (v2) v2 = (mb[t * Tn + s2] != 0);
                unsigned b1 = __ballot_sync(0xffffffffu, v1);
                unsigned b2 = __ballot_sync(0xffffffffu, v2);
                if (lane == 0) mrow[8 * wrp + rr] = ((u64t)b2 << 32) | (u64t)b1;
            }
        }
        cpa_wait0();
        __syncthreads();   // Ks/Vs(ch) + mrow visible; rq ready (first iter)

        // QK^T, kk paired into f32x2
        u64t acc2[4][4] = {};
#pragma unroll 4
        for (int kk = 0; kk < Kd; kk += 2) {
            u64t q2[4], k2[4];
#pragma unroll
            for (int i = 0; i < 4; i++) q2[i] = lds2(&qs[(ty + 16 * i) * KVS + kk]);
#pragma unroll
            for (int j = 0; j < 4; j++) k2[j] = lds2(&Ks[(tx + 16 * j) * KVS + kk]);
#pragma unroll
            for (int i = 0; i < 4; i++)
#pragma unroll
                for (int j = 0; j < 4; j++) acc2[i][j] = fma2(q2[i], k2[j], acc2[i][j]);
        }

        // epilogue: rel-k tap + proximal bias + mask bit + exp
#pragma unroll
        for (int i = 0; i < 4; i++) {
            int q = ty + 16 * i, t = t0 + q;
            u64t rm = mrow[q];
#pragma unroll
            for (int j = 0; j < 4; j++) {
                int sl = tx + 16 * j;
                int s = sbase + ch * 64 + sl;
                int d = s - t;
                int ad = d < 0 ? -d : d;
                float v = lohi_sum(acc2[i][j]);
                if (ad <= WIN) v += rq[q * 12 + d + WIN];
                v -= prox[ad <= BAND ? ad : BAND];
                float e = ((rm >> sl) & 1ull) ? __expf(v) : 0.f;
                P[q * PSTR + sl] = e;
                if (ad <= WIN) pTap[q * 12 + d + WIN] = e;
                lsum[i] += e;
            }
        }
        __syncthreads();   // P visible; all warps done with Ks

        // prefetch next K now -> overlaps the PV phase below
        if (ch + 1 < NCH) {
#pragma unroll
            for (int r = 0; r < 6; r++) {
                int idx = tid + 256 * r;
                int row = idx / 24, c4 = (idx % 24) * 4;
                int s = sbase + (ch + 1) * 64 + row;
                int sc = s < 0 ? 0 : (s >= Tn ? Tn - 1 : s);
                cpa16(&Ks[row * KVS + c4], Kb + sc * Cn + c4);
            }
            cpa_commit();
        }

        // O += P @ V, d-paired (row-major V)
        {
            u64t o2[4][3] = {};
#pragma unroll 2
            for (int sl = 0; sl < 64; sl++) {
                u64t pd[4], v2[3];
#pragma unroll
                for (int i = 0; i < 4; i++) pd[i] = dup2(P[(ty + 16 * i) * PSTR + sl]);
#pragma unroll
                for (int jj = 0; jj < 3; jj++) v2[jj] = lds2(&Vs[sl * KVS + 2 * tx + 32 * jj]);
#pragma unroll
                for (int i = 0; i < 4; i++)
#pragma unroll
                    for (int jj = 0; jj < 3; jj++) o2[i][jj] = fma2(pd[i], v2[jj], o2[i][jj]);
            }
#pragma unroll
            for (int i = 0; i < 4; i++)
#pragma unroll
                for (int jj = 0; jj < 3; jj++) {
                    float2 f = unpk(o2[i][jj]);
                    o[i][2 * jj] += f.x;
                    o[i][2 * jj + 1] += f.y;
                }
        }
        __syncthreads();   // PV done with Vs/P

        // now Vs is free: issue next V
        if (ch + 1 < NCH) {
#pragma unroll
            for (int r = 0; r < 6; r++) {
                int idx = tid + 256 * r;
                int row = idx / 24, c4 = (idx % 24) * 4;
                int s = sbase + (ch + 1) * 64 + row;
                int sc = s < 0 ? 0 : (s >= Tn ? Tn - 1 : s);
                cpa16(&Vs[row * KVS + c4], Vb + sc * Cn + c4);
            }
            cpa_commit();
        }
    }

    // reduce row sums across the 16 tx lanes
#pragma unroll
    for (int i = 0; i < 4; i++) {
        float l = lsum[i];
        l += __shfl_xor_sync(0xffffffffu, l, 1);
        l += __shfl_xor_sync(0xffffffffu, l, 2);
        l += __shfl_xor_sync(0xffffffffu, l, 4);
        l += __shfl_xor_sync(0xffffffffu, l, 8);
        if (tx == 0) lr[ty + 16 * i] = l;
    }
    __syncthreads();

    // rel-V taps + normalize + store
#pragma unroll
    for (int i = 0; i < 4; i++) {
        int q = ty + 16 * i;
        float inv = 1.0f / lr[q];
#pragma unroll
        for (int m = 0; m < 9; m++) {
            float p = pTap[q * 12 + m];
#pragma unroll
            for (int jj = 0; jj < 3; jj++) {
                float2 e2 = *reinterpret_cast<const float2*>(embv + m * Kd + 2 * tx + 32 * jj);
                o[i][2 * jj]     += p * e2.x;
                o[i][2 * jj + 1] += p * e2.y;
            }
        }
        float* ob = g_att + (b * Tn + t0 + q) * Cn + h * Kd;
#pragma unroll
        for (int jj = 0; jj < 3; jj++) {
            float2 w;
            w.x = o[i][2 * jj] * inv;
            w.y = o[i][2 * jj + 1] * inv;
            *reinterpret_cast<float2*>(ob + 2 * tx + 32 * jj) = w;
        }
    }
}

// ---------------------------------------------------------------------------
// Output projection + transpose (R7 version).
// ---------------------------------------------------------------------------
__global__ void __launch_bounds__(256)
outproj_kernel(const float* __restrict__ Wo, const float* __restrict__ bo,
               float* __restrict__ out) {
    extern __shared__ float smp[];
    float* a_s = smp;                // [64 t][OASTR dd]
    float* w_s = smp + 64 * OASTR;   // [64 co][OWSTR dd]
    const int b = blockIdx.z;
    const int t0 = blockIdx.x * 64, c0 = blockIdx.y * 64;
    const int tx = threadIdx.x, ty = threadIdx.y, tid = ty * 16 + tx;
    const int lane = tid & 31, wrp = tid >> 5;
    const int la = lane & 3, kl = lane >> 2;
    const float* ab = g_att + b * Tn * Cn;

#pragma unroll
    for (int r = 0; r < 12; r++) {
        int idx = tid + 256 * r;
        int t = idx / 48, dq = (idx % 48) * 4;
        cpa16(&a_s[t * OASTR + dq], ab + (t0 + t) * Cn + dq);
    }
    cpa_commit();
    {
        float4 vw[12];
#pragma unroll
        for (int r = 0; r < 3; r++)
#pragma unroll
            for (int ph = 0; ph < 4; ph++) {
                int kk = kl + 8 * wrp + 64 * r;
                int d4 = 4 * la + 16 * ph;
                vw[r * 4 + ph] = *reinterpret_cast<const float4*>(Wo + kk * Cn + c0 + d4);
            }
#pragma unroll
        for (int r = 0; r < 3; r++)
#pragma unroll
            for (int ph = 0; ph < 4; ph++) {
                int kk = kl + 8 * wrp + 64 * r;
                int d4 = 4 * la + 16 * ph;
                float4 v = vw[r * 4 + ph];
                w_s[(d4 + 0) * OWSTR + kk] = v.x;
                w_s[(d4 + 1) * OWSTR + kk] = v.y;
                w_s[(d4 + 2) * OWSTR + kk] = v.z;
                w_s[(d4 + 3) * OWSTR + kk] = v.w;
            }
    }
    cpa_wait0();
    __syncthreads();

    u64t acc2[4][4] = {};
#pragma unroll 8
    for (int kk = 0; kk < Cn; kk += 2) {
        u64t w2[4], a2[4];
#pragma unroll
        for (int i = 0; i < 4; i++) w2[i] = lds2(&w_s[(ty + 16 * i) * OWSTR + kk]);
#pragma unroll
        for (int j = 0; j < 4; j++) a2[j] = lds2(&a_s[(tx + 16 * j) * OASTR + kk]);
#pragma unroll
        for (int i = 0; i < 4; i++)
#pragma unroll
            for (int j = 0; j < 4; j++) acc2[i][j] = fma2(w2[i], a2[j], acc2[i][j]);
    }
#pragma unroll
    for (int i = 0; i < 4; i++) {
        int co = c0 + ty + 16 * i;
        float bb = bo[co];
#pragma unroll
        for (int j = 0; j < 4; j++)
            out[(b * Cn + co) * Tn + t0 + tx + 16 * j] = lohi_sum(acc2[i][j]) + bb;
    }
}

// ---------------------------------------------------------------------------
extern "C" void kernel_launch(void* const* d_in, const int* in_sizes, int n_in,
                              void* d_out, int out_size) {
    (void)in_sizes; (void)n_in; (void)out_size;
    const float* x   = (const float*)d_in[0];
    const float* c   = (const float*)d_in[1];
    const float* Wq  = (const float*)d_in[2];
    const float* bq  = (const float*)d_in[3];
    const float* Wk  = (const float*)d_in[4];
    const float* bk  = (const float*)d_in[5];
    const float* Wv  = (const float*)d_in[6];
    const float* bv  = (const float*)d_in[7];
    const float* Wo  = (const float*)d_in[8];
    const float* bo  = (const float*)d_in[9];
    const float* ek  = (const float*)d_in[10];
    const float* ev  = (const float*)d_in[11];
    const int*   msk = (const int*)d_in[12];

    const int attn_smem = ATTN_SMEM_FLOATS * (int)sizeof(float);
    cudaFuncSetAttribute(attn_kernel, cudaFuncAttributeMaxDynamicSharedMemorySize, attn_smem);
    cudaFuncSetAttribute(proj_kernel, cudaFuncAttributeMaxDynamicSharedMemorySize, GEMM_SMEM_BYTES);
    cudaFuncSetAttribute(outproj_kernel, cudaFuncAttributeMaxDynamicSharedMemorySize, OUT_SMEM_BYTES);

    proj_kernel<<<dim3(Tn / 128, Cn / 64, Bn * 3), dim3(16, 16), GEMM_SMEM_BYTES>>>(
        x, c, Wq, bq, Wk, bk, Wv, bv);
    attn_kernel<<<dim3(Tn / TQ, Bn * Hn), dim3(16, 16), attn_smem>>>(ek, ev, msk);
    outproj_kernel<<<dim3(Tn / 64, Cn / 64, Bn), dim3(16, 16), OUT_SMEM_BYTES>>>(
        Wo, bo, (float*)d_out);
}